// round 7
// baseline (speedup 1.0000x reference)
#include <cuda_runtime.h>
#include <math.h>

#define N0 2048
#define D0 3
#define N1 1024
#define D1 5
#define DP0 12                      // padded kn row (floats), 16B-aligned
#define DP1 28

#define TS 32
#define T0 (N0 / TS)                // 64
#define T1 (N1 / TS)                // 32
#define NBLK0 (T0 * (T0 + 1) / 2)   // 2080
#define NBLK1 (T1 * (T1 + 1) / 2)   // 528
#define NBLK  (NBLK0 + NBLK1)       // 2608
#define PAIR_THREADS 256
#define GRID_PAIR 592               // 148 SMs * 4 blocks

typedef unsigned long long ull;

// Scratch (device globals: allocation-free per harness rules)
__device__ __align__(16) float g_knp0[N0 * DP0];   // kn, padded rows
__device__ __align__(16) float g_knp1[N1 * DP1];
__device__ __align__(16) float g_invT0[D0 * D0 * N0];  // -inv, transposed [q*N + i]
__device__ __align__(16) float g_invT1[D1 * D1 * N1];
__device__ double g_sum0;
__device__ double g_sum1;
__device__ unsigned int g_done = 0;

// ---------------- packed f32x2 helpers (FFMA2: PTX-only) ----------------
__device__ __forceinline__ ull f2dup(float v) {
    ull r;
    asm("mov.b64 %0, {%1, %1};" : "=l"(r) : "f"(v));
    return r;
}
__device__ __forceinline__ void f2unpack(ull v, float& lo, float& hi) {
    asm("mov.b64 {%0, %1}, %2;" : "=f"(lo), "=f"(hi) : "l"(v));
}
__device__ __forceinline__ ull fma2(ull a, ull b, ull c) {
    ull d;
    asm("fma.rn.f32x2 %0, %1, %2, %3;" : "=l"(d) : "l"(a), "l"(b), "l"(c));
    return d;
}
__device__ __forceinline__ ull add2(ull a, ull b) {
    ull d;
    asm("add.rn.f32x2 %0, %1, %2;" : "=l"(d) : "l"(a), "l"(b));
    return d;
}

// ---------------- Fused prep: normalize + invert; emit padded kn + negated-transposed inv ----------------
__global__ void __launch_bounds__(32) prep_kernel(const float* __restrict__ k0,
                                                  const float* __restrict__ k1) {
    if (blockIdx.x == 0 && threadIdx.x == 0) {
        g_sum0 = 0.0;
        g_sum1 = 0.0;
    }
    int gid = blockIdx.x * 32 + threadIdx.x;
    if (blockIdx.x < 64) {
        int i = gid;
        float a[9];
        float ss = 0.f;
#pragma unroll
        for (int t = 0; t < 9; t++) {
            a[t] = k0[i * 9 + t];
            ss = fmaf(a[t], a[t], ss);
        }
        float rn = 1.f / (sqrtf(ss) + 1e-8f);
#pragma unroll
        for (int t = 0; t < 9; t++) {
            a[t] *= rn;
            g_knp0[i * DP0 + t] = a[t];
        }
#pragma unroll
        for (int t = 9; t < DP0; t++) g_knp0[i * DP0 + t] = 0.f;

        float inv[9];
        float c00 = a[4] * a[8] - a[5] * a[7];
        float c10 = a[5] * a[6] - a[3] * a[8];
        float c20 = a[3] * a[7] - a[4] * a[6];
        float det = a[0] * c00 + a[1] * c10 + a[2] * c20;
        float id = 1.f / det;
        inv[0] = c00 * id;
        inv[1] = (a[2] * a[7] - a[1] * a[8]) * id;
        inv[2] = (a[1] * a[5] - a[2] * a[4]) * id;
        inv[3] = c10 * id;
        inv[4] = (a[0] * a[8] - a[2] * a[6]) * id;
        inv[5] = (a[2] * a[3] - a[0] * a[5]) * id;
        inv[6] = c20 * id;
        inv[7] = (a[1] * a[6] - a[0] * a[7]) * id;
        inv[8] = (a[0] * a[4] - a[1] * a[3]) * id;
#pragma unroll
        for (int q = 0; q < 9; q++) g_invT0[q * N0 + i] = -inv[q];
    } else {
        int i = gid - 64 * 32;
        float a[5][5], b[5][5];
        float ss = 0.f;
#pragma unroll
        for (int r = 0; r < 5; r++)
#pragma unroll
            for (int c = 0; c < 5; c++) {
                float v = k1[i * 25 + r * 5 + c];
                a[r][c] = v;
                ss = fmaf(v, v, ss);
            }
        float rn = 1.f / (sqrtf(ss) + 1e-8f);
#pragma unroll
        for (int r = 0; r < 5; r++)
#pragma unroll
            for (int c = 0; c < 5; c++) {
                a[r][c] *= rn;
                g_knp1[i * DP1 + r * 5 + c] = a[r][c];
                b[r][c] = (r == c) ? 1.f : 0.f;
            }
#pragma unroll
        for (int t = 25; t < DP1; t++) g_knp1[i * DP1 + t] = 0.f;
#pragma unroll
        for (int col = 0; col < 5; col++) {
#pragma unroll
            for (int r = col + 1; r < 5; r++) {
                bool sw = fabsf(a[r][col]) > fabsf(a[col][col]);
#pragma unroll
                for (int c = 0; c < 5; c++) {
                    float t0 = a[col][c], t1 = a[r][c];
                    a[col][c] = sw ? t1 : t0;
                    a[r][c]   = sw ? t0 : t1;
                    float u0 = b[col][c], u1 = b[r][c];
                    b[col][c] = sw ? u1 : u0;
                    b[r][c]   = sw ? u0 : u1;
                }
            }
            float piv = 1.f / a[col][col];
#pragma unroll
            for (int c = 0; c < 5; c++) {
                a[col][c] *= piv;
                b[col][c] *= piv;
            }
#pragma unroll
            for (int r = 0; r < 5; r++) {
                if (r == col) continue;
                float f = a[r][col];
#pragma unroll
                for (int c = 0; c < 5; c++) {
                    a[r][c] = fmaf(-f, a[col][c], a[r][c]);
                    b[r][c] = fmaf(-f, b[col][c], b[r][c]);
                }
            }
        }
#pragma unroll
        for (int r = 0; r < 5; r++)
#pragma unroll
            for (int c = 0; c < 5; c++)
                g_invT1[(r * 5 + c) * N1 + i] = -b[r][c];
    }
}

// ---------------- One 32x32 pair tile: barrier-free, direct-L1 ----------------
// A: warp-uniform LDG.64 from g_invT (negated, transposed; i-pair contiguous).
// B: per-lane LDG.128 from padded kn rows. No shared memory, no __syncthreads.
template <int D, int DP, int NTOT>
__device__ __forceinline__ void pair_tile(int b, const float* __restrict__ invT,
                                          const float* __restrict__ knp, float& val) {
    constexpr int DD = D * D;

    // triangular decode: b = ti*(ti+1)/2 + tj, tj <= ti
    int ti = (int)((sqrtf(8.f * (float)b + 1.f) - 1.f) * 0.5f);
    while ((ti + 1) * (ti + 2) / 2 <= b) ti++;
    while (ti * (ti + 1) / 2 > b) ti--;
    int tj = b - ti * (ti + 1) / 2;

    const int t = threadIdx.x;
    const int w = t >> 5;   // warp 0..7 -> i range [w*4, w*4+4)
    const int l = t & 31;   // lane -> j
    const int j = tj * TS + l;
    const bool diag = (ti == tj);

    // B = kn[j] via vectorized loads, duplicated into both packed halves
    float Bf[DP];
#pragma unroll
    for (int v = 0; v < DP / 4; v++) {
        float4 f4 = *reinterpret_cast<const float4*>(&knp[j * DP + v * 4]);
        Bf[v * 4 + 0] = f4.x;
        Bf[v * 4 + 1] = f4.y;
        Bf[v * 4 + 2] = f4.z;
        Bf[v * 4 + 3] = f4.w;
    }
    ull B2[DD];
#pragma unroll
    for (int q = 0; q < DD; q++) B2[q] = f2dup(Bf[q]);
    const ull eye2 = f2dup(1.f);

#pragma unroll
    for (int p = 0; p < 2; p++) {
        const int il = w * 4 + 2 * p;
        const int i0 = ti * TS + il;  // even -> 8B-aligned
        ull s2a = 0, s2b = 0;         // two independent accumulator chains
#pragma unroll
        for (int r = 0; r < D; r++) {
            ull A2[D];
#pragma unroll
            for (int k = 0; k < D; k++)  // warp-uniform LDG.64 (broadcast)
                A2[k] = *reinterpret_cast<const ull*>(&invT[(r * D + k) * NTOT + i0]);
#pragma unroll
            for (int c = 0; c < D; c++) {
                ull acc = 0;  // accumulates -C[r][c] (A pre-negated)
#pragma unroll
                for (int k = 0; k < D; k++)
                    acc = fma2(A2[k], B2[k * D + c], acc);
                if (r == c) acc = add2(acc, eye2);  // delta = I - C
                if (c & 1) s2b = fma2(acc, acc, s2b);
                else       s2a = fma2(acc, acc, s2a);
            }
        }
        ull s2 = add2(s2a, s2b);
        float s_lo, s_hi;
        f2unpack(s2, s_lo, s_hi);
        if ((!diag || i0 > j) && s_lo < 1.f) val += 1.f - sqrtf(s_lo);
        if ((!diag || i0 + 1 > j) && s_hi < 1.f) val += 1.f - sqrtf(s_hi);
    }
}

// ---------------- Persistent pair kernel: heavy (D=5) jobs first, barrier-free loop ----------------
__global__ void __launch_bounds__(PAIR_THREADS) pair_all_kernel(float* __restrict__ out) {
    __shared__ float warp_sums[2][PAIR_THREADS / 32];

    float val0 = 0.f, val1 = 0.f;

#pragma unroll 1
    for (int job = blockIdx.x; job < NBLK; job += GRID_PAIR) {
        if (job < NBLK1)  // layer1 (D=5) heavy tiles start first
            pair_tile<D1, DP1, N1>(job, g_invT1, g_knp1, val1);
        else
            pair_tile<D0, DP0, N0>(job - NBLK1, g_invT0, g_knp0, val0);
    }

    // block reduction of both accumulators
#pragma unroll
    for (int off = 16; off > 0; off >>= 1) {
        val0 += __shfl_down_sync(0xFFFFFFFFu, val0, off);
        val1 += __shfl_down_sync(0xFFFFFFFFu, val1, off);
    }
    const int t = threadIdx.x;
    if ((t & 31) == 0) {
        warp_sums[0][t >> 5] = val0;
        warp_sums[1][t >> 5] = val1;
    }
    __syncthreads();
    if (t == 0) {
        float b0 = 0.f, b1 = 0.f;
#pragma unroll
        for (int ww = 0; ww < PAIR_THREADS / 32; ww++) {
            b0 += warp_sums[0][ww];
            b1 += warp_sums[1][ww];
        }
        if (b0 != 0.f) atomicAdd(&g_sum0, (double)b0);
        if (b1 != 0.f) atomicAdd(&g_sum1, (double)b1);
        __threadfence();
        unsigned int done = atomicAdd(&g_done, 1u);
        if (done == GRID_PAIR - 1) {
            __threadfence();
            double s0 = *(volatile double*)&g_sum0;
            double s1 = *(volatile double*)&g_sum1;
            double l0 = 2.0 * s0 / ((double)N0 * (double)(N0 - 1));
            double l1 = 2.0 * s1 / ((double)N1 * (double)(N1 - 1));
            out[0] = (float)(0.5 * (l0 + l1));
            g_done = 0;  // reset for next graph replay
        }
    }
}

extern "C" void kernel_launch(void* const* d_in, const int* in_sizes, int n_in,
                              void* d_out, int out_size) {
    const float* k0 = (const float*)d_in[0];
    const float* k1 = (const float*)d_in[1];
    float* out = (float*)d_out;

    prep_kernel<<<96, 32>>>(k0, k1);
    pair_all_kernel<<<GRID_PAIR, PAIR_THREADS>>>(out);
}

// round 8
// speedup vs baseline: 1.4126x; 1.4126x over previous
#include <cuda_runtime.h>
#include <math.h>

#define N0 2048
#define D0 3
#define N1 1024
#define D1 5

#define TS 32
#define T0 (N0 / TS)                // 64
#define T1 (N1 / TS)                // 32
#define NBLK0 (T0 * (T0 + 1) / 2)   // 2080
#define NBLK1 (T1 * (T1 + 1) / 2)   // 528
#define NBLK  (NBLK0 + NBLK1)       // 2608
#define PAIR_THREADS 256
#define GRID_PAIR 592               // 148 SMs * 4 blocks
#define ATS 34                      // padded stride for transposed A (even: keeps LDS.64 align)
#define PFN 4                       // prefetch regs (covers D=5: 800/256 -> 4)

typedef unsigned long long ull;

// Scratch (device globals: allocation-free per harness rules)
__device__ float g_kn0[N0 * D0 * D0];
__device__ float g_inv0[N0 * D0 * D0];   // stored NEGATED
__device__ float g_kn1[N1 * D1 * D1];
__device__ float g_inv1[N1 * D1 * D1];   // stored NEGATED
__device__ double g_sum0;
__device__ double g_sum1;
__device__ unsigned int g_done = 0;

// ---------------- packed f32x2 helpers (FFMA2: PTX-only) ----------------
__device__ __forceinline__ ull f2dup(float v) {
    ull r;
    asm("mov.b64 %0, {%1, %1};" : "=l"(r) : "f"(v));
    return r;
}
__device__ __forceinline__ void f2unpack(ull v, float& lo, float& hi) {
    asm("mov.b64 {%0, %1}, %2;" : "=f"(lo), "=f"(hi) : "l"(v));
}
__device__ __forceinline__ ull fma2(ull a, ull b, ull c) {
    ull d;
    asm("fma.rn.f32x2 %0, %1, %2, %3;" : "=l"(d) : "l"(a), "l"(b), "l"(c));
    return d;
}
__device__ __forceinline__ ull add2(ull a, ull b) {
    ull d;
    asm("add.rn.f32x2 %0, %1, %2;" : "=l"(d) : "l"(a), "l"(b));
    return d;
}

// ---------------- Fused prep (register-resident, static indices; inv stored negated) ----------------
__global__ void __launch_bounds__(32) prep_kernel(const float* __restrict__ k0,
                                                  const float* __restrict__ k1) {
    if (blockIdx.x == 0 && threadIdx.x == 0) {
        g_sum0 = 0.0;
        g_sum1 = 0.0;
    }
    int gid = blockIdx.x * 32 + threadIdx.x;
    if (blockIdx.x < 64) {
        int i = gid;
        float a[9];
        float ss = 0.f;
#pragma unroll
        for (int t = 0; t < 9; t++) {
            a[t] = k0[i * 9 + t];
            ss = fmaf(a[t], a[t], ss);
        }
        float rn = 1.f / (sqrtf(ss) + 1e-8f);
#pragma unroll
        for (int t = 0; t < 9; t++) {
            a[t] *= rn;
            g_kn0[i * 9 + t] = a[t];
        }
        float c00 = a[4] * a[8] - a[5] * a[7];
        float c10 = a[5] * a[6] - a[3] * a[8];
        float c20 = a[3] * a[7] - a[4] * a[6];
        float det = a[0] * c00 + a[1] * c10 + a[2] * c20;
        float id = -1.f / det;  // negation folded here
        g_inv0[i * 9 + 0] = c00 * id;
        g_inv0[i * 9 + 1] = (a[2] * a[7] - a[1] * a[8]) * id;
        g_inv0[i * 9 + 2] = (a[1] * a[5] - a[2] * a[4]) * id;
        g_inv0[i * 9 + 3] = c10 * id;
        g_inv0[i * 9 + 4] = (a[0] * a[8] - a[2] * a[6]) * id;
        g_inv0[i * 9 + 5] = (a[2] * a[3] - a[0] * a[5]) * id;
        g_inv0[i * 9 + 6] = c20 * id;
        g_inv0[i * 9 + 7] = (a[1] * a[6] - a[0] * a[7]) * id;
        g_inv0[i * 9 + 8] = (a[0] * a[4] - a[1] * a[3]) * id;
    } else {
        int i = gid - 64 * 32;
        float a[5][5], b[5][5];
        float ss = 0.f;
#pragma unroll
        for (int r = 0; r < 5; r++)
#pragma unroll
            for (int c = 0; c < 5; c++) {
                float v = k1[i * 25 + r * 5 + c];
                a[r][c] = v;
                ss = fmaf(v, v, ss);
            }
        float rn = 1.f / (sqrtf(ss) + 1e-8f);
#pragma unroll
        for (int r = 0; r < 5; r++)
#pragma unroll
            for (int c = 0; c < 5; c++) {
                a[r][c] *= rn;
                g_kn1[i * 25 + r * 5 + c] = a[r][c];
                b[r][c] = (r == c) ? 1.f : 0.f;
            }
#pragma unroll
        for (int col = 0; col < 5; col++) {
#pragma unroll
            for (int r = col + 1; r < 5; r++) {
                bool sw = fabsf(a[r][col]) > fabsf(a[col][col]);
#pragma unroll
                for (int c = 0; c < 5; c++) {
                    float t0 = a[col][c], t1 = a[r][c];
                    a[col][c] = sw ? t1 : t0;
                    a[r][c]   = sw ? t0 : t1;
                    float u0 = b[col][c], u1 = b[r][c];
                    b[col][c] = sw ? u1 : u0;
                    b[r][c]   = sw ? u0 : u1;
                }
            }
            float piv = 1.f / a[col][col];
#pragma unroll
            for (int c = 0; c < 5; c++) {
                a[col][c] *= piv;
                b[col][c] *= piv;
            }
#pragma unroll
            for (int r = 0; r < 5; r++) {
                if (r == col) continue;
                float f = a[r][col];
#pragma unroll
                for (int c = 0; c < 5; c++) {
                    a[r][c] = fmaf(-f, a[col][c], a[r][c]);
                    b[r][c] = fmaf(-f, b[col][c], b[r][c]);
                }
            }
        }
#pragma unroll
        for (int r = 0; r < 5; r++)
#pragma unroll
            for (int c = 0; c < 5; c++)
                g_inv1[(r * 5 + c) + i * 25] = -b[r][c];  // negated
    }
}

// ---------------- triangular tile decode ----------------
__device__ __forceinline__ void tri_decode(int b, int& ti, int& tj) {
    ti = (int)((sqrtf(8.f * (float)b + 1.f) - 1.f) * 0.5f);
    while ((ti + 1) * (ti + 2) / 2 <= b) ti++;
    while (ti * (ti + 1) / 2 > b) ti--;
    tj = b - ti * (ti + 1) / 2;
}

// ---------------- prefetch a job's tile data into registers ----------------
__device__ __forceinline__ void prefetch_job(int job, int t, float* pa, float* pb) {
    if (job >= NBLK) return;
    int ti, tj;
    if (job < NBLK1) {  // D=5
        tri_decode(job, ti, tj);
        const float* ia = &g_inv1[ti * TS * 25];
        const float* kb = &g_kn1[tj * TS * 25];
#pragma unroll
        for (int k = 0; k < PFN; k++) {
            int idx = t + k * PAIR_THREADS;
            if (idx < TS * 25) {
                pa[k] = ia[idx];
                pb[k] = kb[idx];
            }
        }
    } else {            // D=3
        tri_decode(job - NBLK1, ti, tj);
        const float* ia = &g_inv0[ti * TS * 9];
        const float* kb = &g_kn0[tj * TS * 9];
#pragma unroll
        for (int k = 0; k < 2; k++) {
            int idx = t + k * PAIR_THREADS;
            if (idx < TS * 9) {
                pa[k] = ia[idx];
                pb[k] = kb[idx];
            }
        }
    }
}

// ---------------- store staged registers into (double-buffered) smem ----------------
template <int D>
__device__ __forceinline__ void store_stage(int t, const float* pa, const float* pb,
                                            float* sAT, float* sB) {
    constexpr int DD = D * D;
    constexpr int KMAX = (TS * DD + PAIR_THREADS - 1) / PAIR_THREADS;
#pragma unroll
    for (int k = 0; k < KMAX; k++) {
        int idx = t + k * PAIR_THREADS;
        if (idx < TS * DD) {
            int i = idx / DD;
            int q = idx - i * DD;
            sAT[q * ATS + i] = pa[k];  // already negated (prep)
            sB[idx] = pb[k];
        }
    }
}

// ---------------- compute one 32x32 tile from smem (R6 body) ----------------
template <int D>
__device__ __forceinline__ void compute_tile(int b, int t, const float* sAT,
                                             const float* sB, float& val) {
    constexpr int DD = D * D;
    int ti, tj;
    tri_decode(b, ti, tj);

    const int w = t >> 5;   // warp 0..7 -> i range [w*4, w*4+4)
    const int l = t & 31;   // lane -> j
    const int j = tj * TS + l;
    const bool diag = (ti == tj);

    ull B2[DD];
#pragma unroll
    for (int q = 0; q < DD; q++) B2[q] = f2dup(sB[l * DD + q]);
    const ull eye2 = f2dup(1.f);

#pragma unroll
    for (int p = 0; p < 2; p++) {
        const int il = w * 4 + 2 * p;  // even -> 8B-aligned LDS.64 broadcast
        ull s2a = 0, s2b = 0;          // two independent accumulator chains
#pragma unroll
        for (int r = 0; r < D; r++) {
            ull A2[D];
#pragma unroll
            for (int k = 0; k < D; k++)
                A2[k] = *reinterpret_cast<const ull*>(&sAT[(r * D + k) * ATS + il]);
#pragma unroll
            for (int c = 0; c < D; c++) {
                ull acc = 0;  // accumulates -C[r][c] (A pre-negated)
#pragma unroll
                for (int k = 0; k < D; k++)
                    acc = fma2(A2[k], B2[k * D + c], acc);
                if (r == c) acc = add2(acc, eye2);  // delta = I - C
                if (c & 1) s2b = fma2(acc, acc, s2b);
                else       s2a = fma2(acc, acc, s2a);
            }
        }
        ull s2 = add2(s2a, s2b);
        float s_lo, s_hi;
        f2unpack(s2, s_lo, s_hi);
        const int i0 = ti * TS + il;
        if ((!diag || i0 > j) && s_lo < 1.f) val += 1.f - sqrtf(s_lo);
        if ((!diag || i0 + 1 > j) && s_hi < 1.f) val += 1.f - sqrtf(s_hi);
    }
}

// ---------------- Persistent, software-pipelined pair kernel ----------------
__global__ void __launch_bounds__(PAIR_THREADS, 4) pair_all_kernel(float* __restrict__ out) {
    __shared__ __align__(16) float sAT[2][D1 * D1 * ATS];
    __shared__ __align__(16) float sB[2][TS * D1 * D1];
    __shared__ float warp_sums[2][PAIR_THREADS / 32];

    const int t = threadIdx.x;
    float val0 = 0.f, val1 = 0.f;

    float pa[PFN], pb[PFN];
    prefetch_job(blockIdx.x, t, pa, pb);

    int buf = 0;
#pragma unroll 1
    for (int job = blockIdx.x; job < NBLK; job += GRID_PAIR) {
        const bool d5 = (job < NBLK1);
        // stage current tile into this iteration's buffer
        if (d5) store_stage<D1>(t, pa, pb, sAT[buf], sB[buf]);
        else    store_stage<D0>(t, pa, pb, sAT[buf], sB[buf]);
        __syncthreads();  // single barrier per tile (double buffer removes WAR bar)
        // prefetch next tile (latency hidden under compute below)
        prefetch_job(job + GRID_PAIR, t, pa, pb);
        // compute current tile
        if (d5) compute_tile<D1>(job, t, sAT[buf], sB[buf], val1);
        else    compute_tile<D0>(job - NBLK1, t, sAT[buf], sB[buf], val0);
        buf ^= 1;
    }

    // block reduction of both accumulators
#pragma unroll
    for (int off = 16; off > 0; off >>= 1) {
        val0 += __shfl_down_sync(0xFFFFFFFFu, val0, off);
        val1 += __shfl_down_sync(0xFFFFFFFFu, val1, off);
    }
    if ((t & 31) == 0) {
        warp_sums[0][t >> 5] = val0;
        warp_sums[1][t >> 5] = val1;
    }
    __syncthreads();
    if (t == 0) {
        float b0 = 0.f, b1 = 0.f;
#pragma unroll
        for (int ww = 0; ww < PAIR_THREADS / 32; ww++) {
            b0 += warp_sums[0][ww];
            b1 += warp_sums[1][ww];
        }
        if (b0 != 0.f) atomicAdd(&g_sum0, (double)b0);
        if (b1 != 0.f) atomicAdd(&g_sum1, (double)b1);
        __threadfence();
        unsigned int done = atomicAdd(&g_done, 1u);
        if (done == GRID_PAIR - 1) {
            __threadfence();
            double s0 = *(volatile double*)&g_sum0;
            double s1 = *(volatile double*)&g_sum1;
            double l0 = 2.0 * s0 / ((double)N0 * (double)(N0 - 1));
            double l1 = 2.0 * s1 / ((double)N1 * (double)(N1 - 1));
            out[0] = (float)(0.5 * (l0 + l1));
            g_done = 0;  // reset for next graph replay
        }
    }
}

extern "C" void kernel_launch(void* const* d_in, const int* in_sizes, int n_in,
                              void* d_out, int out_size) {
    const float* k0 = (const float*)d_in[0];
    const float* k1 = (const float*)d_in[1];
    float* out = (float*)d_out;

    prep_kernel<<<96, 32>>>(k0, k1);
    pair_all_kernel<<<GRID_PAIR, PAIR_THREADS>>>(out);
}